// round 1
// baseline (speedup 1.0000x reference)
#include <cuda_runtime.h>
#include <cuda_bf16.h>
#include <math.h>

// Five global accumulators + completion counter. Zero-initialized at module
// load; the finalizing (last) block resets them after use, so every graph
// replay sees the same initial state. No device allocations anywhere.
__device__ float        g_acc[5];   // p_sum, t_sum, tp_sum, focal_sum, sq_sum
__device__ unsigned int g_count;

#define EPS          1e-6
#define W_DICE       0.6
#define W_TVERSKY    0.2
#define W_FOCAL      0.2
#define W_FTVERSKY   0.2
#define TV_ALPHA     0.5
#define FT_ALPHA     0.7
#define INV_FT_GAMMA 0.75   // 1 / (4/3)
#define BCE_CLAMP    100.0f

__device__ __forceinline__ void accum_elem(float x, float t,
                                           float& s_p, float& s_t, float& s_tp,
                                           float& s_f, float& s_sq) {
    // sigmoid
    float e = __expf(-x);
    float p = __frcp_rn(1.0f + e);

    s_p  += p;
    s_t  += t;
    s_tp  = fmaf(p, t, s_tp);
    s_sq  = fmaf(x, x, s_sq);

    // Binary target: pt = t*p + (1-t)*(1-p) = t*(2p-1) + (1-p)
    float pt = fmaf(t, fmaf(2.0f, p, -1.0f), 1.0f - p);
    // bce = -max(log(pt), -100); pt_ref = exp(-bce) == pt (clamp region < 4e-44)
    float lp  = fmaxf(__logf(pt), -BCE_CLAMP);
    float bce = -lp;
    float om  = 1.0f - pt;
    s_f = fmaf(om * om, bce, s_f);
}

__device__ __forceinline__ float warp_sum(float v) {
    #pragma unroll
    for (int o = 16; o > 0; o >>= 1)
        v += __shfl_down_sync(0xFFFFFFFFu, v, o);
    return v;
}

__global__ void __launch_bounds__(256)
tree_spot_loss_kernel(const float* __restrict__ pred,
                      const float* __restrict__ targ,
                      float* __restrict__ out, int n) {
    float s_p = 0.f, s_t = 0.f, s_tp = 0.f, s_f = 0.f, s_sq = 0.f;

    const int tid    = blockIdx.x * blockDim.x + threadIdx.x;
    const int stride = gridDim.x * blockDim.x;
    const int n4     = n >> 2;

    const float4* __restrict__ p4 = reinterpret_cast<const float4*>(pred);
    const float4* __restrict__ t4 = reinterpret_cast<const float4*>(targ);

    for (int i = tid; i < n4; i += stride) {
        float4 xv = p4[i];
        float4 tv = t4[i];
        accum_elem(xv.x, tv.x, s_p, s_t, s_tp, s_f, s_sq);
        accum_elem(xv.y, tv.y, s_p, s_t, s_tp, s_f, s_sq);
        accum_elem(xv.z, tv.z, s_p, s_t, s_tp, s_f, s_sq);
        accum_elem(xv.w, tv.w, s_p, s_t, s_tp, s_f, s_sq);
    }
    // scalar tail (n not multiple of 4)
    for (int i = (n4 << 2) + tid; i < n; i += stride)
        accum_elem(pred[i], targ[i], s_p, s_t, s_tp, s_f, s_sq);

    // ---- block reduction ----
    __shared__ float sm[5][8];
    const int lane = threadIdx.x & 31;
    const int wid  = threadIdx.x >> 5;

    s_p  = warp_sum(s_p);
    s_t  = warp_sum(s_t);
    s_tp = warp_sum(s_tp);
    s_f  = warp_sum(s_f);
    s_sq = warp_sum(s_sq);
    if (lane == 0) {
        sm[0][wid] = s_p;  sm[1][wid] = s_t; sm[2][wid] = s_tp;
        sm[3][wid] = s_f;  sm[4][wid] = s_sq;
    }
    __syncthreads();

    if (wid == 0) {
        float v0 = (lane < 8) ? sm[0][lane] : 0.f;
        float v1 = (lane < 8) ? sm[1][lane] : 0.f;
        float v2 = (lane < 8) ? sm[2][lane] : 0.f;
        float v3 = (lane < 8) ? sm[3][lane] : 0.f;
        float v4 = (lane < 8) ? sm[4][lane] : 0.f;
        v0 = warp_sum(v0); v1 = warp_sum(v1); v2 = warp_sum(v2);
        v3 = warp_sum(v3); v4 = warp_sum(v4);
        if (lane == 0) {
            atomicAdd(&g_acc[0], v0);
            atomicAdd(&g_acc[1], v1);
            atomicAdd(&g_acc[2], v2);
            atomicAdd(&g_acc[3], v3);
            atomicAdd(&g_acc[4], v4);
            __threadfence();
            unsigned done = atomicAdd(&g_count, 1u);
            if (done == gridDim.x - 1) {
                // ---- finalize (last block) ----
                double N   = (double)n;
                double ps  = g_acc[0];
                double ts  = g_acc[1];
                double tp  = g_acc[2];
                double fs  = g_acc[3];
                double sq  = g_acc[4];

                double dice      = (2.0 * tp + EPS) / (ps + ts + EPS);
                double dice_loss = (ts == 0.0) ? (sq / N) : (1.0 - dice);

                double FP = ps - tp;
                double FN = ts - tp;

                double tv = (tp + EPS) / (tp + TV_ALPHA * FP + (1.0 - TV_ALPHA) * FN + EPS);
                double tversky_loss = 1.0 - tv;

                double focal = fs / N;

                double ftv = (tp + EPS) / (tp + FT_ALPHA * FP + (1.0 - FT_ALPHA) * FN + EPS);
                double focal_tversky = pow(1.0 - ftv, INV_FT_GAMMA);

                double res = W_DICE * dice_loss + W_TVERSKY * tversky_loss
                           + W_FOCAL * focal + W_FTVERSKY * focal_tversky;
                out[0] = (float)res;

                // reset scratch for the next graph replay
                g_acc[0] = 0.f; g_acc[1] = 0.f; g_acc[2] = 0.f;
                g_acc[3] = 0.f; g_acc[4] = 0.f;
                g_count  = 0u;
                __threadfence();
            }
        }
    }
}

extern "C" void kernel_launch(void* const* d_in, const int* in_sizes, int n_in,
                              void* d_out, int out_size) {
    const float* pred = (const float*)d_in[0];
    const float* targ = (const float*)d_in[1];
    float* out = (float*)d_out;
    int n = in_sizes[0];

    const int threads = 256;
    int blocks = (n / 4 + threads - 1) / threads;
    if (blocks > 1024) blocks = 1024;
    if (blocks < 1)    blocks = 1;

    tree_spot_loss_kernel<<<blocks, threads>>>(pred, targ, out, n);
}

// round 3
// speedup vs baseline: 1.0186x; 1.0186x over previous
#include <cuda_runtime.h>
#include <cuda_bf16.h>
#include <math.h>

// Five global accumulators + completion counter. Zero-initialized at module
// load; the finalizing (last) block resets them after use, so every graph
// replay sees the same initial state. No device allocations anywhere.
__device__ float        g_acc[5];   // p_sum, t_sum, tp_sum, focal_sum, sq_sum
__device__ unsigned int g_count;

#define EPS          1e-6
#define W_DICE       0.6
#define W_TVERSKY    0.2
#define W_FOCAL      0.2
#define W_FTVERSKY   0.2
#define TV_ALPHA     0.5
#define FT_ALPHA     0.7
#define INV_FT_GAMMA 0.75   // 1 / (4/3)
#define BCE_CLAMP    100.0f

__device__ __forceinline__ void accum_elem(float x, float t,
                                           float& s_p, float& s_t, float& s_tp,
                                           float& s_f, float& s_sq) {
    // sigmoid
    float e = __expf(-x);
    float p = __frcp_rn(1.0f + e);

    s_p  += p;
    s_t  += t;
    s_tp  = fmaf(p, t, s_tp);
    s_sq  = fmaf(x, x, s_sq);

    // Binary target: pt = t*p + (1-t)*(1-p) = t*(2p-1) + (1-p)
    float pt = fmaf(t, fmaf(2.0f, p, -1.0f), 1.0f - p);
    // bce = -max(log(pt), -100); pt_ref = exp(-bce) == pt (clamp region < 4e-44)
    float lp  = fmaxf(__logf(pt), -BCE_CLAMP);
    float bce = -lp;
    float om  = 1.0f - pt;
    s_f = fmaf(om * om, bce, s_f);
}

__device__ __forceinline__ void accum_f4(float4 xv, float4 tv,
                                         float& s_p, float& s_t, float& s_tp,
                                         float& s_f, float& s_sq) {
    accum_elem(xv.x, tv.x, s_p, s_t, s_tp, s_f, s_sq);
    accum_elem(xv.y, tv.y, s_p, s_t, s_tp, s_f, s_sq);
    accum_elem(xv.z, tv.z, s_p, s_t, s_tp, s_f, s_sq);
    accum_elem(xv.w, tv.w, s_p, s_t, s_tp, s_f, s_sq);
}

__device__ __forceinline__ float warp_sum(float v) {
    #pragma unroll
    for (int o = 16; o > 0; o >>= 1)
        v += __shfl_down_sync(0xFFFFFFFFu, v, o);
    return v;
}

__global__ void __launch_bounds__(256)
tree_spot_loss_kernel(const float* __restrict__ pred,
                      const float* __restrict__ targ,
                      float* __restrict__ out, int n) {
    float s_p = 0.f, s_t = 0.f, s_tp = 0.f, s_f = 0.f, s_sq = 0.f;

    const int tid    = blockIdx.x * blockDim.x + threadIdx.x;
    const int stride = gridDim.x * blockDim.x;
    const int n4     = n >> 2;

    const float4* __restrict__ p4 = reinterpret_cast<const float4*>(pred);
    const float4* __restrict__ t4 = reinterpret_cast<const float4*>(targ);

    int i = tid;
    // Unrolled-by-4 grid-stride loop: 8 independent LDG.128 issued up front
    // per iteration (MLP_p1 ~ 8) before any dependent compute.
    for (; i + 3 * stride < n4; i += 4 * stride) {
        float4 x0 = p4[i];
        float4 x1 = p4[i + stride];
        float4 x2 = p4[i + 2 * stride];
        float4 x3 = p4[i + 3 * stride];
        float4 t0 = t4[i];
        float4 t1 = t4[i + stride];
        float4 t2 = t4[i + 2 * stride];
        float4 t3 = t4[i + 3 * stride];
        accum_f4(x0, t0, s_p, s_t, s_tp, s_f, s_sq);
        accum_f4(x1, t1, s_p, s_t, s_tp, s_f, s_sq);
        accum_f4(x2, t2, s_p, s_t, s_tp, s_f, s_sq);
        accum_f4(x3, t3, s_p, s_t, s_tp, s_f, s_sq);
    }
    // remaining float4s
    for (; i < n4; i += stride) {
        float4 xv = p4[i];
        float4 tv = t4[i];
        accum_f4(xv, tv, s_p, s_t, s_tp, s_f, s_sq);
    }
    // scalar tail (n not multiple of 4)
    for (int j = (n4 << 2) + tid; j < n; j += stride)
        accum_elem(pred[j], targ[j], s_p, s_t, s_tp, s_f, s_sq);

    // ---- block reduction ----
    __shared__ float sm[5][8];
    const int lane = threadIdx.x & 31;
    const int wid  = threadIdx.x >> 5;

    s_p  = warp_sum(s_p);
    s_t  = warp_sum(s_t);
    s_tp = warp_sum(s_tp);
    s_f  = warp_sum(s_f);
    s_sq = warp_sum(s_sq);
    if (lane == 0) {
        sm[0][wid] = s_p;  sm[1][wid] = s_t; sm[2][wid] = s_tp;
        sm[3][wid] = s_f;  sm[4][wid] = s_sq;
    }
    __syncthreads();

    if (wid == 0) {
        float v0 = (lane < 8) ? sm[0][lane] : 0.f;
        float v1 = (lane < 8) ? sm[1][lane] : 0.f;
        float v2 = (lane < 8) ? sm[2][lane] : 0.f;
        float v3 = (lane < 8) ? sm[3][lane] : 0.f;
        float v4 = (lane < 8) ? sm[4][lane] : 0.f;
        v0 = warp_sum(v0); v1 = warp_sum(v1); v2 = warp_sum(v2);
        v3 = warp_sum(v3); v4 = warp_sum(v4);
        if (lane == 0) {
            atomicAdd(&g_acc[0], v0);
            atomicAdd(&g_acc[1], v1);
            atomicAdd(&g_acc[2], v2);
            atomicAdd(&g_acc[3], v3);
            atomicAdd(&g_acc[4], v4);
            __threadfence();
            unsigned done = atomicAdd(&g_count, 1u);
            if (done == gridDim.x - 1) {
                // ---- finalize (last block) ----
                double N   = (double)n;
                double ps  = g_acc[0];
                double ts  = g_acc[1];
                double tp  = g_acc[2];
                double fs  = g_acc[3];
                double sq  = g_acc[4];

                double dice      = (2.0 * tp + EPS) / (ps + ts + EPS);
                double dice_loss = (ts == 0.0) ? (sq / N) : (1.0 - dice);

                double FP = ps - tp;
                double FN = ts - tp;

                double tv = (tp + EPS) / (tp + TV_ALPHA * FP + (1.0 - TV_ALPHA) * FN + EPS);
                double tversky_loss = 1.0 - tv;

                double focal = fs / N;

                double ftv = (tp + EPS) / (tp + FT_ALPHA * FP + (1.0 - FT_ALPHA) * FN + EPS);
                double focal_tversky = pow(1.0 - ftv, INV_FT_GAMMA);

                double res = W_DICE * dice_loss + W_TVERSKY * tversky_loss
                           + W_FOCAL * focal + W_FTVERSKY * focal_tversky;
                out[0] = (float)res;

                // reset scratch for the next graph replay
                g_acc[0] = 0.f; g_acc[1] = 0.f; g_acc[2] = 0.f;
                g_acc[3] = 0.f; g_acc[4] = 0.f;
                g_count  = 0u;
                __threadfence();
            }
        }
    }
}

extern "C" void kernel_launch(void* const* d_in, const int* in_sizes, int n_in,
                              void* d_out, int out_size) {
    const float* pred = (const float*)d_in[0];
    const float* targ = (const float*)d_in[1];
    float* out = (float*)d_out;
    int n = in_sizes[0];

    const int threads = 256;
    const int n4 = n >> 2;
    // Each thread handles 4 float4s per unrolled iteration; target ~2
    // iterations per thread on the 8M-element shape (1024 blocks exactly).
    int blocks = (n4 + threads * 8 - 1) / (threads * 8);
    if (blocks > 1024) blocks = 1024;
    if (blocks < 1)    blocks = 1;

    tree_spot_loss_kernel<<<blocks, threads>>>(pred, targ, out, n);
}

// round 4
// speedup vs baseline: 1.1367x; 1.1159x over previous
#include <cuda_runtime.h>
#include <cuda_bf16.h>
#include <math.h>

// Five global accumulators + completion counter. Zero-initialized at module
// load; the finalizing (last) block resets them after use, so every graph
// replay sees the same initial state. No device allocations anywhere.
__device__ float        g_acc[5];   // p_sum, t_sum, tp_sum, focal_sum, sq_sum
__device__ unsigned int g_count;

#define EPS          1e-6
#define W_DICE       0.6
#define W_TVERSKY    0.2
#define W_FOCAL      0.2
#define W_FTVERSKY   0.2
#define TV_ALPHA     0.5
#define FT_ALPHA     0.7
#define INV_FT_GAMMA 0.75   // 1 / (4/3)
#define BCE_CLAMP    100.0f
#define NEG_LN2      -0.69314718055994531f

__device__ __forceinline__ float frcp_fast(float x) {
    float r;
    asm("rcp.approx.ftz.f32 %0, %1;" : "=f"(r) : "f"(x));
    return r;
}
__device__ __forceinline__ float flg2_fast(float x) {
    float r;
    asm("lg2.approx.ftz.f32 %0, %1;" : "=f"(r) : "f"(x));
    return r;
}

// ~17 thread-instructions per element, 3 MUFU (EX2, RCP, LG2).
__device__ __forceinline__ void accum_elem(float x, float t,
                                           float& s_p, float& s_t, float& s_tp,
                                           float& s_f, float& s_sq) {
    float u = __expf(-x);            // mul + MUFU.EX2
    float p = frcp_fast(1.0f + u);   // add + MUFU.RCP  : sigmoid(x)

    s_p  += p;
    s_t  += t;
    s_tp  = fmaf(p, t, s_tp);
    s_sq  = fmaf(x, x, s_sq);

    // pt = t*p + (1-t)*(1-p)  (binary t) = fma(t, 2p-1, 1-p)
    float omp = 1.0f - p;
    float pt  = fmaf(t, p - omp, omp);
    float om  = 1.0f - pt;
    // bce = min(-log(pt), 100); -log(pt) = lg2(pt) * (-ln2)
    // pt==0 -> lg2=-inf -> product=+inf -> clamps to 100 (matches torch clamp).
    float bce = fminf(flg2_fast(pt) * NEG_LN2, BCE_CLAMP);
    s_f = fmaf(om * om, bce, s_f);
}

__device__ __forceinline__ void accum_f4(float4 xv, float4 tv,
                                         float& s_p, float& s_t, float& s_tp,
                                         float& s_f, float& s_sq) {
    accum_elem(xv.x, tv.x, s_p, s_t, s_tp, s_f, s_sq);
    accum_elem(xv.y, tv.y, s_p, s_t, s_tp, s_f, s_sq);
    accum_elem(xv.z, tv.z, s_p, s_t, s_tp, s_f, s_sq);
    accum_elem(xv.w, tv.w, s_p, s_t, s_tp, s_f, s_sq);
}

__device__ __forceinline__ float warp_sum(float v) {
    #pragma unroll
    for (int o = 16; o > 0; o >>= 1)
        v += __shfl_down_sync(0xFFFFFFFFu, v, o);
    return v;
}

__global__ void __launch_bounds__(256)
tree_spot_loss_kernel(const float* __restrict__ pred,
                      const float* __restrict__ targ,
                      float* __restrict__ out, int n) {
    float s_p = 0.f, s_t = 0.f, s_tp = 0.f, s_f = 0.f, s_sq = 0.f;

    const int tid    = blockIdx.x * blockDim.x + threadIdx.x;
    const int stride = gridDim.x * blockDim.x;
    const int n4     = n >> 2;

    const float4* __restrict__ p4 = reinterpret_cast<const float4*>(pred);
    const float4* __restrict__ t4 = reinterpret_cast<const float4*>(targ);

    int i = tid;
    // Unrolled-by-4 grid-stride loop: 8 independent LDG.128 issued up front
    // per iteration (MLP_p1 ~ 8) before any dependent compute.
    for (; i + 3 * stride < n4; i += 4 * stride) {
        float4 x0 = p4[i];
        float4 x1 = p4[i + stride];
        float4 x2 = p4[i + 2 * stride];
        float4 x3 = p4[i + 3 * stride];
        float4 t0 = t4[i];
        float4 t1 = t4[i + stride];
        float4 t2 = t4[i + 2 * stride];
        float4 t3 = t4[i + 3 * stride];
        accum_f4(x0, t0, s_p, s_t, s_tp, s_f, s_sq);
        accum_f4(x1, t1, s_p, s_t, s_tp, s_f, s_sq);
        accum_f4(x2, t2, s_p, s_t, s_tp, s_f, s_sq);
        accum_f4(x3, t3, s_p, s_t, s_tp, s_f, s_sq);
    }
    // remaining float4s
    for (; i < n4; i += stride) {
        float4 xv = p4[i];
        float4 tv = t4[i];
        accum_f4(xv, tv, s_p, s_t, s_tp, s_f, s_sq);
    }
    // scalar tail (n not multiple of 4)
    for (int j = (n4 << 2) + tid; j < n; j += stride)
        accum_elem(pred[j], targ[j], s_p, s_t, s_tp, s_f, s_sq);

    // ---- block reduction ----
    __shared__ float sm[5][8];
    const int lane = threadIdx.x & 31;
    const int wid  = threadIdx.x >> 5;

    s_p  = warp_sum(s_p);
    s_t  = warp_sum(s_t);
    s_tp = warp_sum(s_tp);
    s_f  = warp_sum(s_f);
    s_sq = warp_sum(s_sq);
    if (lane == 0) {
        sm[0][wid] = s_p;  sm[1][wid] = s_t; sm[2][wid] = s_tp;
        sm[3][wid] = s_f;  sm[4][wid] = s_sq;
    }
    __syncthreads();

    if (wid == 0) {
        float v0 = (lane < 8) ? sm[0][lane] : 0.f;
        float v1 = (lane < 8) ? sm[1][lane] : 0.f;
        float v2 = (lane < 8) ? sm[2][lane] : 0.f;
        float v3 = (lane < 8) ? sm[3][lane] : 0.f;
        float v4 = (lane < 8) ? sm[4][lane] : 0.f;
        v0 = warp_sum(v0); v1 = warp_sum(v1); v2 = warp_sum(v2);
        v3 = warp_sum(v3); v4 = warp_sum(v4);
        if (lane == 0) {
            atomicAdd(&g_acc[0], v0);
            atomicAdd(&g_acc[1], v1);
            atomicAdd(&g_acc[2], v2);
            atomicAdd(&g_acc[3], v3);
            atomicAdd(&g_acc[4], v4);
            __threadfence();
            unsigned done = atomicAdd(&g_count, 1u);
            if (done == gridDim.x - 1) {
                // ---- finalize (last block) ----
                double N   = (double)n;
                double ps  = g_acc[0];
                double ts  = g_acc[1];
                double tp  = g_acc[2];
                double fs  = g_acc[3];
                double sq  = g_acc[4];

                double dice      = (2.0 * tp + EPS) / (ps + ts + EPS);
                double dice_loss = (ts == 0.0) ? (sq / N) : (1.0 - dice);

                double FP = ps - tp;
                double FN = ts - tp;

                double tv = (tp + EPS) / (tp + TV_ALPHA * FP + (1.0 - TV_ALPHA) * FN + EPS);
                double tversky_loss = 1.0 - tv;

                double focal = fs / N;

                double ftv = (tp + EPS) / (tp + FT_ALPHA * FP + (1.0 - FT_ALPHA) * FN + EPS);
                double focal_tversky = pow(1.0 - ftv, INV_FT_GAMMA);

                double res = W_DICE * dice_loss + W_TVERSKY * tversky_loss
                           + W_FOCAL * focal + W_FTVERSKY * focal_tversky;
                out[0] = (float)res;

                // reset scratch for the next graph replay
                g_acc[0] = 0.f; g_acc[1] = 0.f; g_acc[2] = 0.f;
                g_acc[3] = 0.f; g_acc[4] = 0.f;
                g_count  = 0u;
                __threadfence();
            }
        }
    }
}

extern "C" void kernel_launch(void* const* d_in, const int* in_sizes, int n_in,
                              void* d_out, int out_size) {
    const float* pred = (const float*)d_in[0];
    const float* targ = (const float*)d_in[1];
    float* out = (float*)d_out;
    int n = in_sizes[0];

    const int threads = 256;
    const int n4 = n >> 2;
    // Each thread handles 4 float4s per unrolled iteration; target ~2
    // iterations per thread on the 8M-element shape (1024 blocks exactly).
    int blocks = (n4 + threads * 8 - 1) / (threads * 8);
    if (blocks > 1024) blocks = 1024;
    if (blocks < 1)    blocks = 1;

    tree_spot_loss_kernel<<<blocks, threads>>>(pred, targ, out, n);
}

// round 5
// speedup vs baseline: 1.2011x; 1.0567x over previous
#include <cuda_runtime.h>
#include <cuda_bf16.h>
#include <math.h>

// Five global accumulators + completion counter. Zero-initialized at module
// load; the finalizing (last) block resets them after use, so every graph
// replay sees the same initial state. No device allocations anywhere.
__device__ float        g_acc[5];   // p_sum, t_sum, tp_sum, focal_sum, sq_sum
__device__ unsigned int g_count;

#define EPS          1e-6
#define W_DICE       0.6
#define W_TVERSKY    0.2
#define W_FOCAL      0.2
#define W_FTVERSKY   0.2
#define TV_ALPHA     0.5
#define FT_ALPHA     0.7
#define INV_FT_GAMMA 0.75   // 1 / (4/3)
#define BCE_CLAMP    100.0f
#define NEG_LN2      -0.69314718055994531f

__device__ __forceinline__ float frcp_fast(float x) {
    float r;
    asm("rcp.approx.ftz.f32 %0, %1;" : "=f"(r) : "f"(x));
    return r;
}
__device__ __forceinline__ float flg2_fast(float x) {
    float r;
    asm("lg2.approx.ftz.f32 %0, %1;" : "=f"(r) : "f"(x));
    return r;
}

// ~17 thread-instructions per element, 3 MUFU (EX2, RCP, LG2).
__device__ __forceinline__ void accum_elem(float x, float t,
                                           float& s_p, float& s_t, float& s_tp,
                                           float& s_f, float& s_sq) {
    float u = __expf(-x);            // mul + MUFU.EX2
    float p = frcp_fast(1.0f + u);   // add + MUFU.RCP  : sigmoid(x)

    s_p  += p;
    s_t  += t;
    s_tp  = fmaf(p, t, s_tp);
    s_sq  = fmaf(x, x, s_sq);

    // pt = t*p + (1-t)*(1-p)  (binary t) = fma(t, 2p-1, 1-p)
    float omp = 1.0f - p;
    float pt  = fmaf(t, p - omp, omp);
    float om  = 1.0f - pt;
    // bce = min(-log(pt), 100); -log(pt) = lg2(pt) * (-ln2)
    // pt==0 -> lg2=-inf -> product=+inf -> clamps to 100 (matches torch clamp).
    float bce = fminf(flg2_fast(pt) * NEG_LN2, BCE_CLAMP);
    s_f = fmaf(om * om, bce, s_f);
}

__device__ __forceinline__ void accum_f4(float4 xv, float4 tv,
                                         float& s_p, float& s_t, float& s_tp,
                                         float& s_f, float& s_sq) {
    accum_elem(xv.x, tv.x, s_p, s_t, s_tp, s_f, s_sq);
    accum_elem(xv.y, tv.y, s_p, s_t, s_tp, s_f, s_sq);
    accum_elem(xv.z, tv.z, s_p, s_t, s_tp, s_f, s_sq);
    accum_elem(xv.w, tv.w, s_p, s_t, s_tp, s_f, s_sq);
}

__device__ __forceinline__ float warp_sum(float v) {
    #pragma unroll
    for (int o = 16; o > 0; o >>= 1)
        v += __shfl_down_sync(0xFFFFFFFFu, v, o);
    return v;
}

__global__ void __launch_bounds__(256)
tree_spot_loss_kernel(const float* __restrict__ pred,
                      const float* __restrict__ targ,
                      float* __restrict__ out, int n) {
    float s_p = 0.f, s_t = 0.f, s_tp = 0.f, s_f = 0.f, s_sq = 0.f;

    const int tid    = blockIdx.x * blockDim.x + threadIdx.x;
    const int stride = gridDim.x * blockDim.x;
    const int n4     = n >> 2;

    const float4* __restrict__ p4 = reinterpret_cast<const float4*>(pred);
    const float4* __restrict__ t4 = reinterpret_cast<const float4*>(targ);

    int i = tid;
    // Unrolled-by-4 grid-stride loop: 8 independent LDG.128 issued up front
    // per iteration (MLP_p1 ~ 8) before any dependent compute.
    for (; i + 3 * stride < n4; i += 4 * stride) {
        float4 x0 = p4[i];
        float4 x1 = p4[i + stride];
        float4 x2 = p4[i + 2 * stride];
        float4 x3 = p4[i + 3 * stride];
        float4 t0 = t4[i];
        float4 t1 = t4[i + stride];
        float4 t2 = t4[i + 2 * stride];
        float4 t3 = t4[i + 3 * stride];
        accum_f4(x0, t0, s_p, s_t, s_tp, s_f, s_sq);
        accum_f4(x1, t1, s_p, s_t, s_tp, s_f, s_sq);
        accum_f4(x2, t2, s_p, s_t, s_tp, s_f, s_sq);
        accum_f4(x3, t3, s_p, s_t, s_tp, s_f, s_sq);
    }
    // remaining float4s
    for (; i < n4; i += stride) {
        float4 xv = p4[i];
        float4 tv = t4[i];
        accum_f4(xv, tv, s_p, s_t, s_tp, s_f, s_sq);
    }
    // scalar tail (n not multiple of 4)
    for (int j = (n4 << 2) + tid; j < n; j += stride)
        accum_elem(pred[j], targ[j], s_p, s_t, s_tp, s_f, s_sq);

    // ---- block reduction ----
    __shared__ float sm[5][8];
    const int lane = threadIdx.x & 31;
    const int wid  = threadIdx.x >> 5;

    s_p  = warp_sum(s_p);
    s_t  = warp_sum(s_t);
    s_tp = warp_sum(s_tp);
    s_f  = warp_sum(s_f);
    s_sq = warp_sum(s_sq);
    if (lane == 0) {
        sm[0][wid] = s_p;  sm[1][wid] = s_t; sm[2][wid] = s_tp;
        sm[3][wid] = s_f;  sm[4][wid] = s_sq;
    }
    __syncthreads();

    if (wid == 0) {
        float v0 = (lane < 8) ? sm[0][lane] : 0.f;
        float v1 = (lane < 8) ? sm[1][lane] : 0.f;
        float v2 = (lane < 8) ? sm[2][lane] : 0.f;
        float v3 = (lane < 8) ? sm[3][lane] : 0.f;
        float v4 = (lane < 8) ? sm[4][lane] : 0.f;
        v0 = warp_sum(v0); v1 = warp_sum(v1); v2 = warp_sum(v2);
        v3 = warp_sum(v3); v4 = warp_sum(v4);
        if (lane == 0) {
            atomicAdd(&g_acc[0], v0);
            atomicAdd(&g_acc[1], v1);
            atomicAdd(&g_acc[2], v2);
            atomicAdd(&g_acc[3], v3);
            atomicAdd(&g_acc[4], v4);
            __threadfence();
            unsigned done = atomicAdd(&g_count, 1u);
            if (done == gridDim.x - 1) {
                // ---- finalize (last block) ----
                double N   = (double)n;
                double ps  = g_acc[0];
                double ts  = g_acc[1];
                double tp  = g_acc[2];
                double fs  = g_acc[3];
                double sq  = g_acc[4];

                double dice      = (2.0 * tp + EPS) / (ps + ts + EPS);
                double dice_loss = (ts == 0.0) ? (sq / N) : (1.0 - dice);

                double FP = ps - tp;
                double FN = ts - tp;

                double tv = (tp + EPS) / (tp + TV_ALPHA * FP + (1.0 - TV_ALPHA) * FN + EPS);
                double tversky_loss = 1.0 - tv;

                double focal = fs / N;

                double ftv = (tp + EPS) / (tp + FT_ALPHA * FP + (1.0 - FT_ALPHA) * FN + EPS);
                double focal_tversky = pow(1.0 - ftv, INV_FT_GAMMA);

                double res = W_DICE * dice_loss + W_TVERSKY * tversky_loss
                           + W_FOCAL * focal + W_FTVERSKY * focal_tversky;
                out[0] = (float)res;

                // reset scratch for the next graph replay
                g_acc[0] = 0.f; g_acc[1] = 0.f; g_acc[2] = 0.f;
                g_acc[3] = 0.f; g_acc[4] = 0.f;
                g_count  = 0u;
                __threadfence();
            }
        }
    }
}

extern "C" void kernel_launch(void* const* d_in, const int* in_sizes, int n_in,
                              void* d_out, int out_size) {
    const float* pred = (const float*)d_in[0];
    const float* targ = (const float*)d_in[1];
    float* out = (float*)d_out;
    int n = in_sizes[0];

    // Single-wave grid: regs=42 @ 256 threads -> 6 CTAs/SM occupancy limit.
    // blocks = num_SMs * 6 puts every CTA in wave 1; the grid-stride loop
    // absorbs the uneven per-thread trip count. (Host-side attribute query:
    // no allocation, no stream op — graph-capture safe.)
    static int num_sms = 0;
    if (num_sms == 0) {
        int dev = 0;
        cudaGetDevice(&dev);
        cudaDeviceGetAttribute(&num_sms, cudaDevAttrMultiProcessorCount, dev);
        if (num_sms <= 0) num_sms = 148;
    }

    const int threads = 256;
    int blocks = num_sms * 6;
    const int n4 = n >> 2;
    int max_useful = (n4 + threads - 1) / threads;
    if (blocks > max_useful) blocks = max_useful;
    if (blocks < 1) blocks = 1;

    tree_spot_loss_kernel<<<blocks, threads>>>(pred, targ, out, n);
}

// round 6
// speedup vs baseline: 1.2733x; 1.0601x over previous
#include <cuda_runtime.h>
#include <cuda_bf16.h>
#include <math.h>

// Five global accumulators + completion counter. Zero-initialized at module
// load; the finalizing (last) block resets them after use, so every graph
// replay sees the same initial state. No device allocations anywhere.
__device__ float        g_acc[5];   // p_sum, t_sum, tp_sum, focal_sum, sq_sum
__device__ unsigned int g_count;

#define EPS          1e-6
#define W_DICE       0.6
#define W_TVERSKY    0.2
#define W_FOCAL      0.2
#define W_FTVERSKY   0.2
#define TV_ALPHA     0.5
#define FT_ALPHA     0.7
#define INV_FT_GAMMA 0.75   // 1 / (4/3)
#define BCE_CLAMP    100.0f
#define NEG_LN2      -0.69314718055994531f

__device__ __forceinline__ float frcp_fast(float x) {
    float r;
    asm("rcp.approx.ftz.f32 %0, %1;" : "=f"(r) : "f"(x));
    return r;
}
__device__ __forceinline__ float flg2_fast(float x) {
    float r;
    asm("lg2.approx.ftz.f32 %0, %1;" : "=f"(r) : "f"(x));
    return r;
}

// ~17 thread-instructions per element, 3 MUFU (EX2, RCP, LG2).
__device__ __forceinline__ void accum_elem(float x, float t,
                                           float& s_p, float& s_t, float& s_tp,
                                           float& s_f, float& s_sq) {
    float u = __expf(-x);            // mul + MUFU.EX2
    float p = frcp_fast(1.0f + u);   // add + MUFU.RCP  : sigmoid(x)

    s_p  += p;
    s_t  += t;
    s_tp  = fmaf(p, t, s_tp);
    s_sq  = fmaf(x, x, s_sq);

    // pt = t*p + (1-t)*(1-p)  (binary t) = fma(t, 2p-1, 1-p)
    float omp = 1.0f - p;
    float pt  = fmaf(t, p - omp, omp);
    float om  = 1.0f - pt;
    // bce = min(-log(pt), 100); -log(pt) = lg2(pt) * (-ln2)
    // pt==0 -> lg2=-inf -> product=+inf -> clamps to 100 (matches torch clamp).
    float bce = fminf(flg2_fast(pt) * NEG_LN2, BCE_CLAMP);
    s_f = fmaf(om * om, bce, s_f);
}

__device__ __forceinline__ void accum_f4(float4 xv, float4 tv,
                                         float& s_p, float& s_t, float& s_tp,
                                         float& s_f, float& s_sq) {
    accum_elem(xv.x, tv.x, s_p, s_t, s_tp, s_f, s_sq);
    accum_elem(xv.y, tv.y, s_p, s_t, s_tp, s_f, s_sq);
    accum_elem(xv.z, tv.z, s_p, s_t, s_tp, s_f, s_sq);
    accum_elem(xv.w, tv.w, s_p, s_t, s_tp, s_f, s_sq);
}

__device__ __forceinline__ float warp_sum(float v) {
    #pragma unroll
    for (int o = 16; o > 0; o >>= 1)
        v += __shfl_down_sync(0xFFFFFFFFu, v, o);
    return v;
}

__global__ void __launch_bounds__(256)
tree_spot_loss_kernel(const float* __restrict__ pred,
                      const float* __restrict__ targ,
                      float* __restrict__ out, int n) {
    float s_p = 0.f, s_t = 0.f, s_tp = 0.f, s_f = 0.f, s_sq = 0.f;

    const int tid    = blockIdx.x * blockDim.x + threadIdx.x;
    const int stride = gridDim.x * blockDim.x;
    const int step   = stride * 2;
    const int n4     = n >> 2;

    const float4* __restrict__ p4 = reinterpret_cast<const float4*>(pred);
    const float4* __restrict__ t4 = reinterpret_cast<const float4*>(targ);

    int i = tid;
    // Software-pipelined (double-buffered) loop over pairs of float4s:
    // loads for batch k+1 are issued BEFORE the compute of batch k, so each
    // warp always has 4 LDG.128 in flight while its MUFU/FMA chain runs.
    if (i + stride < n4) {
        float4 cx0 = p4[i];
        float4 ct0 = t4[i];
        float4 cx1 = p4[i + stride];
        float4 ct1 = t4[i + stride];
        i += step;
        for (; i + stride < n4; i += step) {
            float4 nx0 = p4[i];
            float4 nt0 = t4[i];
            float4 nx1 = p4[i + stride];
            float4 nt1 = t4[i + stride];
            accum_f4(cx0, ct0, s_p, s_t, s_tp, s_f, s_sq);
            accum_f4(cx1, ct1, s_p, s_t, s_tp, s_f, s_sq);
            cx0 = nx0; ct0 = nt0; cx1 = nx1; ct1 = nt1;
        }
        accum_f4(cx0, ct0, s_p, s_t, s_tp, s_f, s_sq);
        accum_f4(cx1, ct1, s_p, s_t, s_tp, s_f, s_sq);
    }
    // remaining single float4 (if any)
    for (; i < n4; i += stride) {
        float4 xv = p4[i];
        float4 tv = t4[i];
        accum_f4(xv, tv, s_p, s_t, s_tp, s_f, s_sq);
    }
    // scalar tail (n not multiple of 4)
    for (int j = (n4 << 2) + tid; j < n; j += stride)
        accum_elem(pred[j], targ[j], s_p, s_t, s_tp, s_f, s_sq);

    // ---- block reduction ----
    __shared__ float sm[5][8];
    const int lane = threadIdx.x & 31;
    const int wid  = threadIdx.x >> 5;

    s_p  = warp_sum(s_p);
    s_t  = warp_sum(s_t);
    s_tp = warp_sum(s_tp);
    s_f  = warp_sum(s_f);
    s_sq = warp_sum(s_sq);
    if (lane == 0) {
        sm[0][wid] = s_p;  sm[1][wid] = s_t; sm[2][wid] = s_tp;
        sm[3][wid] = s_f;  sm[4][wid] = s_sq;
    }
    __syncthreads();

    if (wid == 0) {
        float v0 = (lane < 8) ? sm[0][lane] : 0.f;
        float v1 = (lane < 8) ? sm[1][lane] : 0.f;
        float v2 = (lane < 8) ? sm[2][lane] : 0.f;
        float v3 = (lane < 8) ? sm[3][lane] : 0.f;
        float v4 = (lane < 8) ? sm[4][lane] : 0.f;
        v0 = warp_sum(v0); v1 = warp_sum(v1); v2 = warp_sum(v2);
        v3 = warp_sum(v3); v4 = warp_sum(v4);
        if (lane == 0) {
            atomicAdd(&g_acc[0], v0);
            atomicAdd(&g_acc[1], v1);
            atomicAdd(&g_acc[2], v2);
            atomicAdd(&g_acc[3], v3);
            atomicAdd(&g_acc[4], v4);
            __threadfence();
            unsigned done = atomicAdd(&g_count, 1u);
            if (done == gridDim.x - 1) {
                // ---- finalize (last block) ----
                double N   = (double)n;
                double ps  = g_acc[0];
                double ts  = g_acc[1];
                double tp  = g_acc[2];
                double fs  = g_acc[3];
                double sq  = g_acc[4];

                double dice      = (2.0 * tp + EPS) / (ps + ts + EPS);
                double dice_loss = (ts == 0.0) ? (sq / N) : (1.0 - dice);

                double FP = ps - tp;
                double FN = ts - tp;

                double tv = (tp + EPS) / (tp + TV_ALPHA * FP + (1.0 - TV_ALPHA) * FN + EPS);
                double tversky_loss = 1.0 - tv;

                double focal = fs / N;

                double ftv = (tp + EPS) / (tp + FT_ALPHA * FP + (1.0 - FT_ALPHA) * FN + EPS);
                double focal_tversky = pow(1.0 - ftv, INV_FT_GAMMA);

                double res = W_DICE * dice_loss + W_TVERSKY * tversky_loss
                           + W_FOCAL * focal + W_FTVERSKY * focal_tversky;
                out[0] = (float)res;

                // reset scratch for the next graph replay
                g_acc[0] = 0.f; g_acc[1] = 0.f; g_acc[2] = 0.f;
                g_acc[3] = 0.f; g_acc[4] = 0.f;
                g_count  = 0u;
                __threadfence();
            }
        }
    }
}

extern "C" void kernel_launch(void* const* d_in, const int* in_sizes, int n_in,
                              void* d_out, int out_size) {
    const float* pred = (const float*)d_in[0];
    const float* targ = (const float*)d_in[1];
    float* out = (float*)d_out;
    int n = in_sizes[0];

    // Single-wave grid at 4 CTAs/SM: safe for any reg count <= 64, so the
    // whole grid is wave 1 regardless of the exact allocation. The pipelined
    // grid-stride loop absorbs the uneven per-thread trip count.
    static int num_sms = 0;
    if (num_sms == 0) {
        int dev = 0;
        cudaGetDevice(&dev);
        cudaDeviceGetAttribute(&num_sms, cudaDevAttrMultiProcessorCount, dev);
        if (num_sms <= 0) num_sms = 148;
    }

    const int threads = 256;
    int blocks = num_sms * 4;
    const int n4 = n >> 2;
    int max_useful = (n4 + threads - 1) / threads;
    if (blocks > max_useful) blocks = max_useful;
    if (blocks < 1) blocks = 1;

    tree_spot_loss_kernel<<<blocks, threads>>>(pred, targ, out, n);
}